// round 1
// baseline (speedup 1.0000x reference)
#include <cuda_runtime.h>

// Problem dims (fixed by the reference)
#define HH 128
#define WW 256
#define BB 8
#define NFUSED (BB*64*HH*WW)   // 16,777,216

constexpr int TILE_W = 64;
constexpr int TILE_H = 8;
constexpr int CI_BLK = 8;
constexpr int CO_BLK = 8;
constexpr int NTHR   = 128;    // blockDim (32,4)

// Scratch activations (static device allocation — allowed)
__device__ float  g_h1 [BB*32*HH*WW];
__device__ float  g_mid[BB*16*HH*WW];
__device__ float  g_h2 [BB*32*HH*WW];
__device__ double g_loss_acc;

__global__ void zero_loss_kernel() { g_loss_acc = 0.0; }

// Direct 3x3 SAME conv + bias + ReLU. If LOSS, instead of writing the output,
// accumulate sum((ref - out)^2) into g_loss_acc.
template<int CI, int CO, bool LOSS>
__launch_bounds__(NTHR)
__global__ void conv3x3_kernel(const float* __restrict__ in,
                               const float* __restrict__ wgt,
                               const float* __restrict__ bias,
                               float* __restrict__ out,
                               const float* __restrict__ ref)
{
    __shared__ float s_in[CI_BLK][TILE_H+2][TILE_W+2];
    __shared__ float s_w [CO_BLK][CI_BLK][9];

    const int tx  = threadIdx.x;          // 0..31
    const int ty  = threadIdx.y;          // 0..3
    const int tid = ty*32 + tx;
    const int x0  = blockIdx.x * TILE_W;
    const int y0  = blockIdx.y * TILE_H;
    constexpr int NCO_CH = CO / CO_BLK;
    const int b   = blockIdx.z / NCO_CH;
    const int co0 = (blockIdx.z % NCO_CH) * CO_BLK;

    float acc[CO_BLK][4];
#pragma unroll
    for (int c = 0; c < CO_BLK; c++)
#pragma unroll
        for (int p = 0; p < 4; p++) acc[c][p] = 0.f;

    for (int ci0 = 0; ci0 < CI; ci0 += CI_BLK) {
        // Stage weights for this (co-chunk, ci-chunk)
        for (int i = tid; i < CO_BLK*CI_BLK*9; i += NTHR) {
            int co = i/(CI_BLK*9); int r = i%(CI_BLK*9); int ci = r/9; int k = r%9;
            s_w[co][ci][k] = wgt[((co0+co)*CI + (ci0+ci))*9 + k];
        }
        // Stage input tile with halo (zero-padded at borders)
        constexpr int TP = (TILE_H+2)*(TILE_W+2);
        for (int i = tid; i < CI_BLK*TP; i += NTHR) {
            int ci = i/TP; int r = i%TP;
            int yy = r/(TILE_W+2), xx = r%(TILE_W+2);
            int gy = y0 + yy - 1, gx = x0 + xx - 1;
            float v = 0.f;
            if ((unsigned)gy < HH && (unsigned)gx < WW)
                v = in[(((size_t)b*CI + ci0+ci)*HH + gy)*WW + gx];
            s_in[ci][yy][xx] = v;
        }
        __syncthreads();

#pragma unroll
        for (int ci = 0; ci < CI_BLK; ci++) {
            // 4 pixels per thread: (ty,tx),(ty,tx+32),(ty+4,tx),(ty+4,tx+32)
            float v[4][9];
#pragma unroll
            for (int dy = 0; dy < 3; dy++)
#pragma unroll
                for (int dx = 0; dx < 3; dx++) {
                    v[0][dy*3+dx] = s_in[ci][ty  +dy][tx   +dx];
                    v[1][dy*3+dx] = s_in[ci][ty  +dy][tx+32+dx];
                    v[2][dy*3+dx] = s_in[ci][ty+4+dy][tx   +dx];
                    v[3][dy*3+dx] = s_in[ci][ty+4+dy][tx+32+dx];
                }
#pragma unroll
            for (int co = 0; co < CO_BLK; co++) {
#pragma unroll
                for (int k = 0; k < 9; k++) {
                    float wv = s_w[co][ci][k];
                    acc[co][0] = fmaf(v[0][k], wv, acc[co][0]);
                    acc[co][1] = fmaf(v[1][k], wv, acc[co][1]);
                    acc[co][2] = fmaf(v[2][k], wv, acc[co][2]);
                    acc[co][3] = fmaf(v[3][k], wv, acc[co][3]);
                }
            }
        }
        __syncthreads();
    }

    float lsum = 0.f;
#pragma unroll
    for (int co = 0; co < CO_BLK; co++) {
        float bv = __ldg(&bias[co0+co]);
        size_t chb = ((size_t)b*CO + co0+co)*HH;
        size_t i0  = (chb + y0+ty  )*WW + x0 + tx;
        size_t i2  = (chb + y0+ty+4)*WW + x0 + tx;
        float o0 = fmaxf(acc[co][0] + bv, 0.f);
        float o1 = fmaxf(acc[co][1] + bv, 0.f);
        float o2 = fmaxf(acc[co][2] + bv, 0.f);
        float o3 = fmaxf(acc[co][3] + bv, 0.f);
        if (LOSS) {
            float d0 = ref[i0]    - o0;
            float d1 = ref[i0+32] - o1;
            float d2 = ref[i2]    - o2;
            float d3 = ref[i2+32] - o3;
            lsum += d0*d0 + d1*d1 + d2*d2 + d3*d3;
        } else {
            out[i0]    = o0;
            out[i0+32] = o1;
            out[i2]    = o2;
            out[i2+32] = o3;
        }
    }

    if (LOSS) {
#pragma unroll
        for (int off = 16; off > 0; off >>= 1)
            lsum += __shfl_down_sync(0xffffffffu, lsum, off);
        __shared__ float s_red[4];
        if ((tid & 31) == 0) s_red[tid >> 5] = lsum;
        __syncthreads();
        if (tid == 0)
            atomicAdd(&g_loss_acc,
                      (double)(s_red[0] + s_red[1] + s_red[2] + s_red[3]));
    }
}

// fused_feat = 0.5*(feat0 + feat1)  (exact algebraic reduction of the
// cross-modal attention: weights2 is identical across m, so softmax over m
// is exactly 0.5 each).
__global__ void fuse_avg_kernel(const float4* __restrict__ a,
                                const float4* __restrict__ b,
                                float4* __restrict__ o, int n4)
{
    int i = blockIdx.x * blockDim.x + threadIdx.x;
    if (i < n4) {
        float4 x = a[i], y = b[i];
        o[i] = make_float4(0.5f*(x.x+y.x), 0.5f*(x.y+y.y),
                           0.5f*(x.z+y.z), 0.5f*(x.w+y.w));
    }
}

__global__ void finalize_kernel(float* out, int begin, int end)
{
    float loss = (float)(g_loss_acc * (1.0 / (double)NFUSED));
    for (int i = begin + (int)threadIdx.x; i < end; i += (int)blockDim.x)
        out[i] = loss;
}

extern "C" void kernel_launch(void* const* d_in, const int* in_sizes, int n_in,
                              void* d_out, int out_size)
{
    const float* feat0 = (const float*)d_in[0];
    const float* feat1 = (const float*)d_in[1];
    const float* w1 = (const float*)d_in[2];  const float* b1 = (const float*)d_in[3];
    const float* w2 = (const float*)d_in[4];  const float* b2 = (const float*)d_in[5];
    const float* w3 = (const float*)d_in[6];  const float* b3 = (const float*)d_in[7];
    const float* w4 = (const float*)d_in[8];  const float* b4 = (const float*)d_in[9];
    float* out = (float*)d_out;

    float *h1, *mid, *h2;
    cudaGetSymbolAddress((void**)&h1,  g_h1);
    cudaGetSymbolAddress((void**)&mid, g_mid);
    cudaGetSymbolAddress((void**)&h2,  g_h2);

    dim3 blk(32, 4);
    dim3 g1(WW/TILE_W, HH/TILE_H, BB*(32/CO_BLK));  // conv1: 64->32
    dim3 g2(WW/TILE_W, HH/TILE_H, BB*(16/CO_BLK));  // conv2: 32->16
    dim3 g3(WW/TILE_W, HH/TILE_H, BB*(32/CO_BLK));  // conv3: 16->32
    dim3 g4(WW/TILE_W, HH/TILE_H, BB*(64/CO_BLK));  // conv4: 32->64 (+loss)

    zero_loss_kernel<<<1, 1>>>();

    const float* feats[2] = {feat0, feat1};
    for (int m = 0; m < 2; m++) {
        const float* f = feats[m];
        conv3x3_kernel<64, 32, false><<<g1, blk>>>(f,   w1, b1, h1,  nullptr);
        conv3x3_kernel<32, 16, false><<<g2, blk>>>(h1,  w2, b2, mid, nullptr);
        conv3x3_kernel<16, 32, false><<<g3, blk>>>(mid, w3, b3, h2,  nullptr);
        conv3x3_kernel<32, 64, true ><<<g4, blk>>>(h2,  w4, b4, nullptr, f);
    }

    // fused_feat = average of the two modalities
    int n4 = NFUSED / 4;
    fuse_avg_kernel<<<(n4 + 255) / 256, 256>>>(
        (const float4*)feat0, (const float4*)feat1, (float4*)out, n4);

    // auto_enc_loss goes after the fused tensor in the flattened output
    if (out_size > NFUSED)
        finalize_kernel<<<1, 32>>>(out, NFUSED, out_size);
}

// round 2
// speedup vs baseline: 1.5483x; 1.5483x over previous
#include <cuda_runtime.h>
#include <cstdint>

#define HH 128
#define WW 256
#define BB 8
#define HW (HH*WW)
#define NFUSED (BB*64*HH*WW)   // 16,777,216

constexpr int TW   = 64;    // tile width  (output cols per block)
constexpr int TH   = 8;     // tile height (output rows per block)
constexpr int CIB  = 8;     // input channels per chunk
constexpr int COT  = 16;    // output channels per block
constexpr int CP   = COT/2; // co pairs
constexpr int NTHR = 128;   // blockDim (32,4)
constexpr int TILE_ELEMS = CIB * 10 * 66;  // 5280 floats per input chunk

// Scratch activations (static device allocation — allowed)
__device__ float  g_h1 [BB*32*HW];
__device__ float  g_mid[BB*16*HW];
__device__ float  g_h2 [BB*32*HW];
__device__ double g_loss_acc;

__global__ void zero_loss_kernel() { g_loss_acc = 0.0; }

// ---- packed f32x2 helpers ------------------------------------------------
__device__ __forceinline__ unsigned long long dup2(float v) {
    unsigned long long r;
    asm("mov.b64 %0, {%1, %1};" : "=l"(r) : "f"(v));
    return r;
}
__device__ __forceinline__ unsigned long long ffma2(unsigned long long a,
                                                    unsigned long long b,
                                                    unsigned long long c) {
    unsigned long long d;
    asm("fma.rn.f32x2 %0, %1, %2, %3;" : "=l"(d) : "l"(a), "l"(b), "l"(c));
    return d;
}
__device__ __forceinline__ void unpack2(unsigned long long p, float& lo, float& hi) {
    asm("mov.b64 {%0, %1}, %2;" : "=f"(lo), "=f"(hi) : "l"(p));
}
__device__ __forceinline__ uint32_t s2u(const void* p) {
    return (uint32_t)__cvta_generic_to_shared(p);
}
__device__ __forceinline__ void cp_async4(uint32_t saddr, const void* gaddr, int srcsz) {
    asm volatile("cp.async.ca.shared.global [%0], [%1], 4, %2;"
                 :: "r"(saddr), "l"(gaddr), "r"(srcsz));
}
__device__ __forceinline__ void cp_commit() {
    asm volatile("cp.async.commit_group;" ::: "memory");
}
__device__ __forceinline__ void cp_wait1() {
    asm volatile("cp.async.wait_group 1;" ::: "memory");
}

// ---- direct 3x3 SAME conv + bias + ReLU, FFMA2 co-paired -----------------
// Block: tile 64x8 pixels, 16 output channels. Grid z = b * (CO/16) + co_chunk.
// If LOSS: accumulate sum((ref - out)^2) into g_loss_acc instead of writing.
template<int CI, int CO, bool LOSS>
__global__ void __launch_bounds__(NTHR, 4)
conv3x3_kernel(const float* __restrict__ in,
               const float* __restrict__ wgt,
               const float* __restrict__ bias,
               float* __restrict__ out,
               const float* __restrict__ ref)
{
    __shared__ float  s_in[2][CIB][10][66];
    __shared__ float2 s_w [2][CIB][9][CP];

    const int tx  = threadIdx.x;           // 0..31
    const int ty  = threadIdx.y;           // 0..3
    const int tid = ty*32 + tx;
    const int x0  = blockIdx.x * TW;
    const int y0  = blockIdx.y * TH;
    constexpr int ZCO = CO / COT;
    const int b   = blockIdx.z / ZCO;
    const int co0 = (blockIdx.z % ZCO) * COT;
    const float* inb = in + (size_t)b*CI*HW;

    constexpr int NC = CI / CIB;

    // acc[pair j][pixel p], pixels: 0=(ty,tx) 1=(ty,tx+32) 2=(ty+4,tx) 3=(ty+4,tx+32)
    unsigned long long acc[CP][4];
#pragma unroll
    for (int j = 0; j < CP; j++)
#pragma unroll
        for (int p = 0; p < 4; p++) acc[j][p] = 0ull;

    auto stage = [&](int chunk, int buf) {
        // input tile chunk via cp.async (zfill halo)
        const float* src0 = inb + (size_t)chunk*CIB*HW;
        uint32_t sbase = s2u(&s_in[buf][0][0][0]);
        for (int i = tid; i < TILE_ELEMS; i += NTHR) {
            int ci = i / 660; int r = i - ci*660;
            int yy = r / 66;  int xx = r - yy*66;
            int gy = y0 + yy - 1, gx = x0 + xx - 1;
            bool ok = ((unsigned)gy < HH) & ((unsigned)gx < WW);
            const float* g = ok ? (src0 + ci*HW + gy*WW + gx) : src0;
            cp_async4(sbase + i*4, g, ok ? 4 : 0);
        }
        // weights, co-paired: s_w[ci][k][j] = (w[co0+2j], w[co0+2j+1])
        for (int i = tid; i < CIB*9*CP*2; i += NTHR) {
            int h = i & 1; int p = i >> 1;
            int j = p % CP; int q = p / CP;    // q = ci*9 + k
            int k = q % 9;  int ci = q / 9;
            int co = co0 + 2*j + h;
            ((float*)&s_w[buf][ci][k][j])[h] =
                wgt[((size_t)co*CI + chunk*CIB + ci)*9 + k];
        }
    };

    stage(0, 0);
    cp_commit();

#pragma unroll 1
    for (int c = 0; c < NC; c++) {
        const int buf = c & 1;
        if (c + 1 < NC) stage(c + 1, buf ^ 1);
        cp_commit();
        cp_wait1();
        __syncthreads();

#pragma unroll 2
        for (int ci = 0; ci < CIB; ci++) {
#pragma unroll
            for (int dy = 0; dy < 3; dy++) {
                const float* r0 = &s_in[buf][ci][ty + dy    ][tx];
                const float* r1 = &s_in[buf][ci][ty + dy + 4][tx];
                unsigned long long v0 = dup2(r0[0]),  v1 = dup2(r0[1]),  v2 = dup2(r0[2]);
                unsigned long long v3 = dup2(r0[32]), v4 = dup2(r0[33]), v5 = dup2(r0[34]);
                unsigned long long v6 = dup2(r1[0]),  v7 = dup2(r1[1]),  v8 = dup2(r1[2]);
                unsigned long long v9 = dup2(r1[32]), va = dup2(r1[33]), vb = dup2(r1[34]);
                const unsigned long long* w0p =
                    (const unsigned long long*)&s_w[buf][ci][dy*3 + 0][0];
                const unsigned long long* w1p =
                    (const unsigned long long*)&s_w[buf][ci][dy*3 + 1][0];
                const unsigned long long* w2p =
                    (const unsigned long long*)&s_w[buf][ci][dy*3 + 2][0];
#pragma unroll
                for (int j = 0; j < CP; j++) {
                    unsigned long long w0 = w0p[j], w1 = w1p[j], w2 = w2p[j];
                    acc[j][0] = ffma2(v0, w0, acc[j][0]);
                    acc[j][0] = ffma2(v1, w1, acc[j][0]);
                    acc[j][0] = ffma2(v2, w2, acc[j][0]);
                    acc[j][1] = ffma2(v3, w0, acc[j][1]);
                    acc[j][1] = ffma2(v4, w1, acc[j][1]);
                    acc[j][1] = ffma2(v5, w2, acc[j][1]);
                    acc[j][2] = ffma2(v6, w0, acc[j][2]);
                    acc[j][2] = ffma2(v7, w1, acc[j][2]);
                    acc[j][2] = ffma2(v8, w2, acc[j][2]);
                    acc[j][3] = ffma2(v9, w0, acc[j][3]);
                    acc[j][3] = ffma2(va, w1, acc[j][3]);
                    acc[j][3] = ffma2(vb, w2, acc[j][3]);
                }
            }
        }
        __syncthreads();
    }

    // epilogue: bias + relu, then store or loss
    float lsum = 0.f;
#pragma unroll
    for (int j = 0; j < CP; j++) {
        float blo = __ldg(&bias[co0 + 2*j]);
        float bhi = __ldg(&bias[co0 + 2*j + 1]);
        size_t chlo = ((size_t)b*CO + co0 + 2*j) * HW;
#pragma unroll
        for (int p = 0; p < 4; p++) {
            int row = y0 + ty + (p >> 1)*4;
            int col = x0 + tx + (p & 1)*32;
            size_t idx = chlo + (size_t)row*WW + col;
            float alo, ahi;
            unpack2(acc[j][p], alo, ahi);
            float olo = fmaxf(alo + blo, 0.f);
            float ohi = fmaxf(ahi + bhi, 0.f);
            if (LOSS) {
                float dlo = ref[idx]      - olo;
                float dhi = ref[idx + HW] - ohi;
                lsum += dlo*dlo + dhi*dhi;
            } else {
                out[idx]      = olo;
                out[idx + HW] = ohi;
            }
        }
    }

    if (LOSS) {
#pragma unroll
        for (int off = 16; off > 0; off >>= 1)
            lsum += __shfl_down_sync(0xffffffffu, lsum, off);
        __shared__ float s_red[4];
        if ((tid & 31) == 0) s_red[tid >> 5] = lsum;
        __syncthreads();
        if (tid == 0)
            atomicAdd(&g_loss_acc,
                      (double)(s_red[0] + s_red[1] + s_red[2] + s_red[3]));
    }
}

// fused_feat = 0.5*(feat0 + feat1)  (exact algebraic reduction of the
// cross-modal attention: second-stage logits are identical across m, so
// softmax over m is exactly 0.5 each).
__global__ void fuse_avg_kernel(const float4* __restrict__ a,
                                const float4* __restrict__ b,
                                float4* __restrict__ o, int n4)
{
    int i = blockIdx.x * blockDim.x + threadIdx.x;
    if (i < n4) {
        float4 x = a[i], y = b[i];
        o[i] = make_float4(0.5f*(x.x+y.x), 0.5f*(x.y+y.y),
                           0.5f*(x.z+y.z), 0.5f*(x.w+y.w));
    }
}

__global__ void finalize_kernel(float* out, int begin, int end)
{
    float loss = (float)(g_loss_acc * (1.0 / (double)NFUSED));
    for (int i = begin + (int)threadIdx.x; i < end; i += (int)blockDim.x)
        out[i] = loss;
}

extern "C" void kernel_launch(void* const* d_in, const int* in_sizes, int n_in,
                              void* d_out, int out_size)
{
    const float* feat0 = (const float*)d_in[0];
    const float* feat1 = (const float*)d_in[1];
    const float* w1 = (const float*)d_in[2];  const float* b1 = (const float*)d_in[3];
    const float* w2 = (const float*)d_in[4];  const float* b2 = (const float*)d_in[5];
    const float* w3 = (const float*)d_in[6];  const float* b3 = (const float*)d_in[7];
    const float* w4 = (const float*)d_in[8];  const float* b4 = (const float*)d_in[9];
    float* out = (float*)d_out;

    float *h1, *mid, *h2;
    cudaGetSymbolAddress((void**)&h1,  g_h1);
    cudaGetSymbolAddress((void**)&mid, g_mid);
    cudaGetSymbolAddress((void**)&h2,  g_h2);

    dim3 blk(32, 4);
    dim3 g1(4, 16, BB * (32/COT));   // conv1: 64 -> 32
    dim3 g2(4, 16, BB * (16/COT==0?1:16/COT));  // conv2: 32 -> 16 (ZCO=1)
    dim3 g3(4, 16, BB * (32/COT));   // conv3: 16 -> 32
    dim3 g4(4, 16, BB * (64/COT));   // conv4: 32 -> 64 (+loss)

    zero_loss_kernel<<<1, 1>>>();

    const float* feats[2] = {feat0, feat1};
    for (int m = 0; m < 2; m++) {
        const float* f = feats[m];
        conv3x3_kernel<64, 32, false><<<g1, blk>>>(f,   w1, b1, h1,  nullptr);
        conv3x3_kernel<32, 16, false><<<g2, blk>>>(h1,  w2, b2, mid, nullptr);
        conv3x3_kernel<16, 32, false><<<g3, blk>>>(mid, w3, b3, h2,  nullptr);
        conv3x3_kernel<32, 64, true ><<<g4, blk>>>(h2,  w4, b4, nullptr, f);
    }

    // fused_feat = average of the two modalities
    int n4 = NFUSED / 4;
    fuse_avg_kernel<<<(n4 + 255) / 256, 256>>>(
        (const float4*)feat0, (const float4*)feat1, (float4*)out, n4);

    // auto_enc_loss goes after the fused tensor in the flattened output
    if (out_size > NFUSED)
        finalize_kernel<<<1, 32>>>(out, NFUSED, out_size);
}